// round 10
// baseline (speedup 1.0000x reference)
#include <cuda_runtime.h>
#include <cstdint>

// SpecEMA decoupled-lookback scan, resident 296-block grid, 3-buffer TMA
// software pipeline: load(i+2) and store(i) overlap compute/lookback(i+1).
#define BB 64
#define CC 2
#define TT 4000
#define FF 96
#define NF4 24
#define NSUB 8
#define LS 5
#define LCH (NSUB * LS)        // 40
#define NCH (TT / LCH)         // 100
#define NTHR (NSUB * NF4)      // 192
#define NITEMS (BB * NCH)      // 6400
#define GRIDP 296              // 2/SM on 148 SMs; fully resident on 148 & 152
#define NBUF 3
#define TILE_C_BYTES (LCH * FF * 4)           // 15360 per channel
#define DSMEM (NBUF * CC * TILE_C_BYTES)      // 92160

#define ALPHA_F 0.99f
#define OMA_F ((float)(1.0 - 0.99))   // float32(1 - 0.99), matches jax

__host__ __device__ constexpr float fpow(float a, int n) {
    float r = 1.0f;
    for (int i = 0; i < n; i++) r *= a;
    return r;
}

// ---- scratch (__device__ globals; allocation-free; zero-initialized) ----
__device__ float4 g_agg[NITEMS * NF4];
__device__ float4 g_inc[NITEMS * NF4];
__device__ unsigned g_flag[NITEMS];  // gen-coded: 2*gen+1 = agg, 2*gen+2 = inc
__device__ unsigned g_ctr;           // +GRIDP per launch -> uniform generation

__device__ __forceinline__ unsigned ld_acquire(const unsigned* p) {
    unsigned v;
    asm volatile("ld.global.acquire.gpu.b32 %0, [%1];" : "=r"(v) : "l"(p));
    return v;
}
__device__ __forceinline__ void st_release(unsigned* p, unsigned v) {
    asm volatile("st.global.release.gpu.b32 [%0], %1;" :: "l"(p), "r"(v));
}
__device__ __forceinline__ uint32_t smem_u32(const void* p) {
    return (uint32_t)__cvta_generic_to_shared(p);
}
__device__ __forceinline__ void mbar_init(uint32_t mbar, uint32_t cnt) {
    asm volatile("mbarrier.init.shared.b64 [%0], %1;" :: "r"(mbar), "r"(cnt) : "memory");
}
__device__ __forceinline__ void mbar_expect_tx(uint32_t mbar, uint32_t bytes) {
    asm volatile("mbarrier.arrive.expect_tx.shared.b64 _, [%0], %1;"
                 :: "r"(mbar), "r"(bytes) : "memory");
}
__device__ __forceinline__ void mbar_wait(uint32_t mbar, uint32_t parity) {
    asm volatile(
        "{\n\t.reg .pred P1;\n\t"
        "WAIT_LOOP_%=:\n\t"
        "mbarrier.try_wait.parity.acquire.cta.shared::cta.b64 P1, [%0], %1, 0x989680;\n\t"
        "@P1 bra.uni WAIT_DONE_%=;\n\t"
        "bra.uni WAIT_LOOP_%=;\n\t"
        "WAIT_DONE_%=:\n\t}"
        :: "r"(mbar), "r"(parity) : "memory");
}
__device__ __forceinline__ void bulk_ld(uint32_t smem_dst, const void* gsrc,
                                        uint32_t bytes, uint32_t mbar) {
    asm volatile("cp.async.bulk.shared::cta.global.mbarrier::complete_tx::bytes "
                 "[%0], [%1], %2, [%3];"
                 :: "r"(smem_dst), "l"(gsrc), "r"(bytes), "r"(mbar) : "memory");
}
__device__ __forceinline__ void bulk_st(void* gdst, uint32_t smem_src, uint32_t bytes) {
    asm volatile("cp.async.bulk.global.shared::cta.bulk_group [%0], [%1], %2;"
                 :: "l"(gdst), "r"(smem_src), "r"(bytes) : "memory");
}

#define EMA4(s, a, c)                                                        \
    (s).x = fmaf(fmaf((a).x, (a).x, (c).x * (c).x), OMA_F, (s).x * ALPHA_F); \
    (s).y = fmaf(fmaf((a).y, (a).y, (c).y * (c).y), OMA_F, (s).y * ALPHA_F); \
    (s).z = fmaf(fmaf((a).z, (a).z, (c).z * (c).z), OMA_F, (s).z * ALPHA_F); \
    (s).w = fmaf(fmaf((a).w, (a).w, (c).w * (c).w), OMA_F, (s).w * ALPHA_F)

// NOTE: parameter tokens W_/V_/S_/P_ chosen so they can never collide with
// float4 member names (.x .y .z .w) during macro expansion (R9 bug).
#define FMA4(acc, W_, V_)                      \
    (acc).x = fmaf((W_), (V_).x, (acc).x);     \
    (acc).y = fmaf((W_), (V_).y, (acc).y);     \
    (acc).z = fmaf((W_), (V_).z, (acc).z);     \
    (acc).w = fmaf((W_), (V_).w, (acc).w)

#define FOLD4(S_, A_, P_)                      \
    (S_).x = fmaf((A_), (S_).x, (P_).x);       \
    (S_).y = fmaf((A_), (S_).y, (P_).y);       \
    (S_).z = fmaf((A_), (S_).z, (P_).z);       \
    (S_).w = fmaf((A_), (S_).w, (P_).w)

__global__ void __launch_bounds__(NTHR, 2)
k_scan(const float* __restrict__ x,
       const float* __restrict__ state,
       float* __restrict__ out,
       float* __restrict__ fstate,
       int write_state) {
    extern __shared__ float4 xs[];            // [NBUF][CC][LCH][NF4]
    __shared__ float4 sP[NSUB][NF4];
    __shared__ uint64_t mbar[NBUF];
    __shared__ unsigned s_gen;

    const int tid = threadIdx.x;
    const int bid = blockIdx.x;
    if (tid == 0) {
        s_gen = atomicAdd(&g_ctr, 1u) / (unsigned)GRIDP;
#pragma unroll
        for (int q = 0; q < NBUF; q++) mbar_init(smem_u32(&mbar[q]), 1);
    }
    __syncthreads();
    const unsigned gen = s_gen;
    const unsigned V_AGG = 2u * gen + 1u;
    const unsigned V_INC = 2u * gen + 2u;

    const int f4  = tid % NF4;
    const int sub = tid / NF4;
    const float aLS = fpow(ALPHA_F, LS);
    const float aB  = fpow(ALPHA_F, LCH);

    const int nitems = (NITEMS - bid + GRIDP - 1) / GRIDP;

    #define XBUF(q, c) (xs + (q) * (CC * LCH * NF4) + (c) * (LCH * NF4))

    // ---- prologue: prefetch items 0 and 1 ----
    if (tid == 0) {
#pragma unroll
        for (int i = 0; i < 2; i++) {
            if (i < nitems) {
                int w = bid + i * GRIDP;
                int b = w % BB, j = w / BB;
                int g0 = ((b * CC + 0) * TT + j * LCH) * FF;
                int g1 = ((b * CC + 1) * TT + j * LCH) * FF;
                mbar_expect_tx(smem_u32(&mbar[i]), 2 * TILE_C_BYTES);
                bulk_ld(smem_u32(XBUF(i, 0)), x + g0, TILE_C_BYTES, smem_u32(&mbar[i]));
                bulk_ld(smem_u32(XBUF(i, 1)), x + g1, TILE_C_BYTES, smem_u32(&mbar[i]));
            }
        }
    }

    for (int i = 0; i < nitems; i++) {
        const int q = i % NBUF;
        const unsigned par = (unsigned)((i / NBUF) & 1);
        const int w = bid + i * GRIDP;
        const int b = w % BB, j = w / BB;
        const int ch = b * NCH + j;

        mbar_wait(smem_u32(&mbar[q]), par);

        // ---- phase 1: per-sub partial EMA from s=0 ----
        float4* x0 = XBUF(q, 0);
        float4* x1 = XBUF(q, 1);
        float4 P = make_float4(0.f, 0.f, 0.f, 0.f);
#pragma unroll
        for (int t = 0; t < LS; t++) {
            float4 a = x0[(sub * LS + t) * NF4 + f4];
            float4 c = x1[(sub * LS + t) * NF4 + f4];
            EMA4(P, a, c);
        }
        sP[sub][f4] = P;
        __syncthreads();

        float4 A = sP[0][f4];
#pragma unroll
        for (int k = 1; k < NSUB; k++) {
            float4 t4 = sP[k][f4];
            FOLD4(A, aLS, t4);
        }

        if (sub == 0) {                       // tids 0..23, warp 0
            g_agg[ch * NF4 + f4] = A;
            __syncwarp(0x00FFFFFFu);
            if (tid == 0) { __threadfence(); st_release(&g_flag[ch], V_AGG); }
        }

        // ---- phase 2: barrier-free lookback ----
        float4 S;
        if (j == 0) {
            S = *(const float4*)(state + f4 * 4);
        } else {
            float4 acc = make_float4(0.f, 0.f, 0.f, 0.f);
            float wgt = 1.0f;
            int k = j - 1;
            for (;;) {
                const unsigned* fl = &g_flag[b * NCH + k];
                unsigned st = ld_acquire(fl);
                int spins = 0;
                while (st < V_AGG) {
                    if (++spins > 8) { __nanosleep(128); spins = 0; }
                    st = ld_acquire(fl);
                }
                if (st == V_INC) {
                    float4 v = g_inc[(b * NCH + k) * NF4 + f4];
                    FMA4(acc, wgt, v);
                    break;
                }
                float4 v = g_agg[(b * NCH + k) * NF4 + f4];
                FMA4(acc, wgt, v);
                wgt *= aB;
                if (k == 0) {
                    float4 s0 = *(const float4*)(state + f4 * 4);
                    FMA4(acc, wgt, s0);
                    break;
                }
                k--;
            }
            S = acc;
        }

        // ---- publish inclusive ASAP ----
        if (sub == 0) {
            float4 inc;
            inc.x = fmaf(aB, S.x, A.x);
            inc.y = fmaf(aB, S.y, A.y);
            inc.z = fmaf(aB, S.z, A.z);
            inc.w = fmaf(aB, S.w, A.w);
            g_inc[ch * NF4 + f4] = inc;
            __syncwarp(0x00FFFFFFu);
            if (tid == 0) { __threadfence(); st_release(&g_flag[ch], V_INC); }
        }

        // ---- start state for this sub-chunk ----
        float4 s4 = S;
#pragma unroll
        for (int k = 0; k < NSUB - 1; k++) {
            if (k < sub) {
                float4 Pk = sP[k][f4];
                FOLD4(s4, aLS, Pk);
            }
        }

        // ---- phase 3: replay, y in place in smem ----
#pragma unroll
        for (int t = 0; t < LS; t++) {
            float4 a = x0[(sub * LS + t) * NF4 + f4];
            float4 c = x1[(sub * LS + t) * NF4 + f4];
            EMA4(s4, a, c);
            float4 r;
            r.x = rsqrtf(s4.x); r.y = rsqrtf(s4.y);
            r.z = rsqrtf(s4.z); r.w = rsqrtf(s4.w);
            float4 y0, y1;
            y0.x = a.x * r.x; y0.y = a.y * r.y; y0.z = a.z * r.z; y0.w = a.w * r.w;
            y1.x = c.x * r.x; y1.y = c.y * r.y; y1.z = c.z * r.z; y1.w = c.w * r.w;
            x0[(sub * LS + t) * NF4 + f4] = y0;
            x1[(sub * LS + t) * NF4 + f4] = y1;
        }

        if (write_state && j == NCH - 1 && sub == NSUB - 1) {
            *(float4*)(fstate + b * FF + f4 * 4) = s4;
        }

        __syncthreads();
        asm volatile("fence.proxy.async.shared::cta;" ::: "memory");
        if (tid == 0) {
            const int g0 = ((b * CC + 0) * TT + j * LCH) * FF;
            const int g1 = ((b * CC + 1) * TT + j * LCH) * FF;
            bulk_st(out + g0, smem_u32(XBUF(q, 0)), TILE_C_BYTES);
            bulk_st(out + g1, smem_u32(XBUF(q, 1)), TILE_C_BYTES);
            asm volatile("cp.async.bulk.commit_group;" ::: "memory");

            // prefetch item i+2 into buffer (i+2)%3; its previous occupant
            // (item i-1) was stored a full iteration ago -> wait_group 1
            const int i2 = i + 2;
            if (i2 < nitems) {
                asm volatile("cp.async.bulk.wait_group 1;" ::: "memory");
                const int w2 = bid + i2 * GRIDP;
                const int b2 = w2 % BB, j2 = w2 / BB;
                const int q2 = i2 % NBUF;
                const int h0 = ((b2 * CC + 0) * TT + j2 * LCH) * FF;
                const int h1 = ((b2 * CC + 1) * TT + j2 * LCH) * FF;
                mbar_expect_tx(smem_u32(&mbar[q2]), 2 * TILE_C_BYTES);
                bulk_ld(smem_u32(XBUF(q2, 0)), x + h0, TILE_C_BYTES, smem_u32(&mbar[q2]));
                bulk_ld(smem_u32(XBUF(q2, 1)), x + h1, TILE_C_BYTES, smem_u32(&mbar[q2]));
            }
        }
    }

    // drain outstanding stores before CTA teardown
    if (tid == 0) {
        asm volatile("cp.async.bulk.wait_group 0;" ::: "memory");
    }
}

extern "C" void kernel_launch(void* const* d_in, const int* in_sizes, int n_in,
                              void* d_out, int out_size) {
    const float* feat  = (const float*)d_in[0];   // [B,C,T,F] f32
    const float* state = (const float*)d_in[1];   // [1,1,F]   f32
    float* out = (float*)d_out;

    const int n_out_main = BB * CC * TT * FF;     // 49,152,000
    int write_state = (out_size >= n_out_main + BB * FF) ? 1 : 0;
    float* fstate = out + n_out_main;

    cudaFuncSetAttribute(k_scan, cudaFuncAttributeMaxDynamicSharedMemorySize, DSMEM);
    k_scan<<<GRIDP, NTHR, DSMEM>>>(feat, state, out, fstate, write_state);
}